// round 8
// baseline (speedup 1.0000x reference)
#include <cuda_runtime.h>
#include <cuda_bf16.h>
#include <cstdint>

// ArcFace loss, fused. INT8 IMMA GEMM (m16n8k32.s8, base sm_80 feature —
// tcgen05 unavailable at compute_103 base). Per-row symmetric quantization of
// normalized x and W; exact fp32 target logit recomputed in k3.
// B=512, D=512, C=64000.
constexpr int BB = 512;
constexpr int DD = 512;
constexpr int CC = 64000;

constexpr int BM = 128, BN = 128, BK = 64;   // BK in elements (=bytes, int8)
constexpr int MT = BB / BM;    // 4
constexpr int NT = CC / BN;    // 500
constexpr int NSTG = DD / BK;  // 8
constexpr int RSTRIDE = 80;    // smem row stride bytes (64 data + 16 pad): ldsm conflict-free
constexpr int STG = BM * RSTRIDE;  // 10240 B per operand stage
constexpr int NPIPE = 4;

// dynamic smem layout
constexpr int A_OFF  = 0;                      // 4 stages
constexpr int B_OFF  = NPIPE * STG;            // 40960, 4 stages
constexpr int SY_OFF = B_OFF + NPIPE * STG;    // 81920: 128 ints
constexpr int SA_OFF = SY_OFF + 512;           // 82432: 128 floats (1/s_a)
constexpr int SW_OFF = SA_OFF + 512;           // 82944: 128 floats (1/s_w)
constexpr int RA_OFF = SW_OFF + 512;           // 83456: 128x4 floats
constexpr int SMEM_TOTAL = RA_OFF + 2048;      // 85504 (x2 CTA = 171KB <= 228KB)

__device__ float  g_xn[BB * DD];          // normalized x fp32 (k3 exact dot)
__device__ int8_t g_xq[BB * DD];          // quantized normalized x
__device__ float  g_isa[BB];              // per-row 1/s_a = max|row|/127
__device__ int8_t g_wq[CC * DD];          // quantized normalized W
__device__ float  g_isw[CC];              // per-row 1/s_w
__device__ int    g_y[BB];
__device__ float  g_partial[MT * NT * BM];
__device__ double g_term[BB];

// ---------------- PTX helpers ----------------
__device__ __forceinline__ void ldsm4(uint32_t* r, uint32_t a) {
    asm volatile("ldmatrix.sync.aligned.m8n8.x4.shared.b16 {%0,%1,%2,%3}, [%4];"
        : "=r"(r[0]), "=r"(r[1]), "=r"(r[2]), "=r"(r[3]) : "r"(a));
}
__device__ __forceinline__ void imma16832(int* c, const uint32_t* a, uint32_t b0, uint32_t b1) {
    asm volatile("mma.sync.aligned.m16n8k32.row.col.s32.s8.s8.s32 "
        "{%0,%1,%2,%3}, {%4,%5,%6,%7}, {%8,%9}, {%0,%1,%2,%3};"
        : "+r"(c[0]), "+r"(c[1]), "+r"(c[2]), "+r"(c[3])
        : "r"(a[0]), "r"(a[1]), "r"(a[2]), "r"(a[3]), "r"(b0), "r"(b1));
}
__device__ __forceinline__ void cpasync16(uint32_t smem, const void* gptr) {
    asm volatile("cp.async.cg.shared.global [%0], [%1], 16;"
        :: "r"(smem), "l"(gptr) : "memory");
}
__device__ __forceinline__ void cpcommit() { asm volatile("cp.async.commit_group;" ::: "memory"); }
__device__ __forceinline__ void cpwait2() { asm volatile("cp.async.wait_group 2;" ::: "memory"); }

// ---------------------------------------------------------------------------
__global__ void k0_decode_y(const int* __restrict__ yw) {
    __shared__ int oddnz;
    int t = threadIdx.x;
    if (t == 0) oddnz = 0;
    __syncthreads();
    if (t < 256 && yw[2 * t + 1] != 0) atomicOr(&oddnz, 1);
    __syncthreads();
    if (oddnz == 0) g_y[t] = (int)((const long long*)yw)[t];
    else            g_y[t] = yw[t];
}

// ---------------------------------------------------------------------------
// k1: L2-normalize rows of x -> fp32 + per-row-scaled int8. 512 blocks x 128.
// ---------------------------------------------------------------------------
__global__ void k1_norm_x(const float* __restrict__ x) {
    int row = blockIdx.x;
    int t = threadIdx.x; // 128
    float4 v = ((const float4*)(x + row * DD))[t];
    float ss = v.x * v.x + v.y * v.y + v.z * v.z + v.w * v.w;
    float mx = fmaxf(fmaxf(fabsf(v.x), fabsf(v.y)), fmaxf(fabsf(v.z), fabsf(v.w)));
    #pragma unroll
    for (int o = 16; o; o >>= 1) {
        ss += __shfl_xor_sync(0xffffffffu, ss, o);
        mx = fmaxf(mx, __shfl_xor_sync(0xffffffffu, mx, o));
    }
    __shared__ float ws[4], wm[4];
    if ((t & 31) == 0) { ws[t >> 5] = ss; wm[t >> 5] = mx; }
    __syncthreads();
    float tot = ws[0] + ws[1] + ws[2] + ws[3];
    float gmx = fmaxf(fmaxf(wm[0], wm[1]), fmaxf(wm[2], wm[3]));
    float sc = 1.0f / fmaxf(sqrtf(tot), 1e-12f);
    float4 o4 = make_float4(v.x * sc, v.y * sc, v.z * sc, v.w * sc);
    ((float4*)(g_xn + row * DD))[t] = o4;
    float nmx = gmx * sc;                       // max |normalized element|
    float s = 127.0f / fmaxf(nmx, 1e-12f);
    char4 q;
    q.x = (char)max(-127, min(127, __float2int_rn(o4.x * s)));
    q.y = (char)max(-127, min(127, __float2int_rn(o4.y * s)));
    q.z = (char)max(-127, min(127, __float2int_rn(o4.z * s)));
    q.w = (char)max(-127, min(127, __float2int_rn(o4.w * s)));
    ((char4*)(g_xq + row * DD))[t] = q;
    if (t == 0) g_isa[row] = nmx / 127.0f;      // 1/s
}

// ---------------------------------------------------------------------------
// k1b: L2-normalize rows of W -> per-row-scaled int8. One warp per row.
// ---------------------------------------------------------------------------
__global__ __launch_bounds__(256) void k1b_norm_w(const float* __restrict__ Wm) {
    int wid = threadIdx.x >> 5, lane = threadIdx.x & 31;
    int row = blockIdx.x * 8 + wid;
    const float4* wr = (const float4*)(Wm + (size_t)row * DD);
    float4 v[4];
    float ss = 0.f, mx = 0.f;
    #pragma unroll
    for (int i = 0; i < 4; i++) {
        v[i] = wr[lane + i * 32];
        ss += v[i].x * v[i].x + v[i].y * v[i].y + v[i].z * v[i].z + v[i].w * v[i].w;
        mx = fmaxf(mx, fmaxf(fmaxf(fabsf(v[i].x), fabsf(v[i].y)),
                             fmaxf(fabsf(v[i].z), fabsf(v[i].w))));
    }
    #pragma unroll
    for (int o = 16; o; o >>= 1) {
        ss += __shfl_xor_sync(0xffffffffu, ss, o);
        mx = fmaxf(mx, __shfl_xor_sync(0xffffffffu, mx, o));
    }
    float sc = 1.0f / fmaxf(sqrtf(ss), 1e-12f);
    float nmx = mx * sc;
    float s = 127.0f / fmaxf(nmx, 1e-12f);
    char q[16];
    #pragma unroll
    for (int i = 0; i < 4; i++) {
        q[i * 4 + 0] = (char)max(-127, min(127, __float2int_rn(v[i].x * sc * s)));
        q[i * 4 + 1] = (char)max(-127, min(127, __float2int_rn(v[i].y * sc * s)));
        q[i * 4 + 2] = (char)max(-127, min(127, __float2int_rn(v[i].z * sc * s)));
        q[i * 4 + 3] = (char)max(-127, min(127, __float2int_rn(v[i].w * sc * s)));
    }
    // lane stores 16 contiguous bytes at elem offset (lane*4 per float4 block):
    // v[i] was row elems [ (lane + i*32)*4 .. +3 ] -> scatter as 4B chunks
    int8_t* out = g_wq + (size_t)row * DD;
    #pragma unroll
    for (int i = 0; i < 4; i++)
        *(int*)(out + (lane + i * 32) * 4) = *(int*)&q[i * 4];
    if (lane == 0) g_isw[row] = nmx / 127.0f;
}

// ---------------------------------------------------------------------------
// k2: IMMA GEMM, 256 threads / 8 warps (2x4, warp tile 64x32), 128Mx128N,
// BK=64 (two k32 chunks), 4-stage cp.async single-sync pipeline, 2 CTAs/SM.
// Epilogue: theta = acc*isa*isw; exp + target mask + row-sum -> g_partial.
// ---------------------------------------------------------------------------
__global__ __launch_bounds__(256, 2) void k2_gemm() {
    extern __shared__ char smem[];
    const uint32_t sb = (uint32_t)__cvta_generic_to_shared(smem);
    const int t = threadIdx.x, lane = t & 31, wp = t >> 5;
    const int wm = wp >> 2, wn = wp & 3;
    const int mt = blockIdx.x, nt = blockIdx.y;
    const int m0 = mt * BM, n0 = nt * BN;

    if (t < BM) {
        ((int*)(smem + SY_OFF))[t]   = g_y[m0 + t];
        ((float*)(smem + SA_OFF))[t] = g_isa[m0 + t];
        ((float*)(smem + SW_OFF))[t] = g_isw[n0 + t];
    }

    // producers: 2 threads/row (128 rows), each 2x16B chunks
    const int pr = t >> 1, pc = (t & 1) * 32;
    const int8_t* gA = g_xq + (m0 + pr) * DD + pc;
    const int8_t* gB = g_wq + (size_t)(n0 + pr) * DD + pc;
    const uint32_t sA = sb + A_OFF + pr * RSTRIDE + pc;
    const uint32_t sB = sb + B_OFF + pr * RSTRIDE + pc;
    uint32_t wo = 0;

    auto fill = [&]() {
        cpasync16(sA + wo, gA);
        cpasync16(sA + wo + 16, gA + 16);
        cpasync16(sB + wo, gB);
        cpasync16(sB + wo + 16, gB + 16);
        gA += BK; gB += BK;
        wo += STG; if (wo == NPIPE * STG) wo = 0;
    };

    int acc[4][4][4];
    #pragma unroll
    for (int i = 0; i < 4; i++)
        #pragma unroll
        for (int j = 0; j < 4; j++)
            #pragma unroll
            for (int k = 0; k < 4; k++) acc[i][j][k] = 0;

    uint32_t aoff[4], boff[2];
    #pragma unroll
    for (int mf = 0; mf < 4; mf++)
        aoff[mf] = sb + A_OFF + (wm * 64 + mf * 16 + (lane & 15)) * RSTRIDE + (lane >> 4) * 16;
    #pragma unroll
    for (int g = 0; g < 2; g++)
        boff[g] = sb + B_OFF + (wn * 32 + g * 16 + (lane & 15)) * RSTRIDE + (lane >> 4) * 16;

    fill(); cpcommit();
    fill(); cpcommit();
    fill(); cpcommit();

    uint32_t ro = 0;
    for (int ks = 0; ks < NSTG; ks++) {
        cpwait2();
        __syncthreads();
        if (ks + 3 < NSTG) fill();
        cpcommit();

        #pragma unroll
        for (int kc = 0; kc < 2; kc++) {   // two k32 chunks (32 bytes apart)
            uint32_t bfrag[2][4];
            ldsm4(bfrag[0], boff[0] + ro + kc * 32);
            ldsm4(bfrag[1], boff[1] + ro + kc * 32);
            #pragma unroll
            for (int mf = 0; mf < 4; mf++) {
                uint32_t afrag[4];
                ldsm4(afrag, aoff[mf] + ro + kc * 32);
                #pragma unroll
                for (int nf = 0; nf < 4; nf++) {
                    int g = nf >> 1, h = nf & 1;
                    imma16832(acc[mf][nf], afrag, bfrag[g][h], bfrag[g][2 + h]);
                }
            }
        }
        ro += STG; if (ro == NPIPE * STG) ro = 0;
    }
    __syncthreads();

    // epilogue
    const int*   sy  = (const int*)(smem + SY_OFF);
    const float* ssa = (const float*)(smem + SA_OFF);
    const float* ssw = (const float*)(smem + SW_OFF);
    float* rowacc = (float*)(smem + RA_OFF);
    float wsc[4][2];
    #pragma unroll
    for (int nf = 0; nf < 4; nf++) {
        int nl = wn * 32 + nf * 8 + (lane & 3) * 2;
        wsc[nf][0] = ssw[nl];
        wsc[nf][1] = ssw[nl + 1];
    }
    #pragma unroll
    for (int mf = 0; mf < 4; mf++) {
        #pragma unroll
        for (int h = 0; h < 2; h++) {
            int row = wm * 64 + mf * 16 + h * 8 + (lane >> 2);
            int yrel = sy[row] - n0;
            float fa = 64.0f * ssa[row];
            float rsum = 0.f;
            #pragma unroll
            for (int nf = 0; nf < 4; nf++) {
                int nl = wn * 32 + nf * 8 + (lane & 3) * 2;
                float e0 = __expf(fa * wsc[nf][0] * (float)acc[mf][nf][h * 2]);
                float e1 = __expf(fa * wsc[nf][1] * (float)acc[mf][nf][h * 2 + 1]);
                rsum += (nl     == yrel) ? 0.f : e0;
                rsum += (nl + 1 == yrel) ? 0.f : e1;
            }
            rsum += __shfl_xor_sync(0xffffffffu, rsum, 1);
            rsum += __shfl_xor_sync(0xffffffffu, rsum, 2);
            if ((lane & 3) == 0) rowacc[row * 4 + wn] = rsum;
        }
    }
    __syncthreads();
    if (t < BM)
        g_partial[(mt * NT + nt) * BM + t] =
            (rowacc[t * 4] + rowacc[t * 4 + 1]) + (rowacc[t * 4 + 2] + rowacc[t * 4 + 3]);
}

// ---------------------------------------------------------------------------
// k3: per-row finalize; exact fp32 target logit. One block per row, 512 thr.
// ---------------------------------------------------------------------------
__global__ __launch_bounds__(512) void k3_final(const float* __restrict__ Wm) {
    __shared__ double sd[512];
    __shared__ float  sf[128], sg[128];
    int b = blockIdx.x, t = threadIdx.x;
    int yb = g_y[b];
    int mt = b >> 7, ml = b & 127;

    double ex = (t < NT) ? (double)g_partial[(mt * NT + t) * BM + ml] : 0.0;

    if (t < 128) {
        float4 wv = ((const float4*)(Wm + (size_t)yb * DD))[t];
        float4 xv = ((const float4*)(g_xn + b * DD))[t];
        sf[t] = wv.x * xv.x + wv.y * xv.y + wv.z * xv.z + wv.w * xv.w;
        sg[t] = wv.x * wv.x + wv.y * wv.y + wv.z * wv.z + wv.w * wv.w;
    }
    sd[t] = ex;
    __syncthreads();
    for (int s = 256; s >= 128; s >>= 1) {
        if (t < s) sd[t] += sd[t + s];
        __syncthreads();
    }
    for (int s = 64; s; s >>= 1) {
        if (t < s) { sd[t] += sd[t + s]; sf[t] += sf[t + s]; sg[t] += sg[t + s]; }
        __syncthreads();
    }
    if (t == 0) {
        double tgt = (double)sf[0] / fmax(sqrt((double)sg[0]), 1e-12);
        double tc = fmin(fmax(tgt, -1.0 + 1e-7), 1.0 - 1e-7);
        double num = 64.0 * cos(acos(tc) + 0.5);
        double den = exp(num) + sd[0];
        g_term[b] = num - log(den);
    }
}

__global__ void k4_reduce(float* __restrict__ out) {
    __shared__ double sm[BB];
    int t = threadIdx.x;
    sm[t] = g_term[t];
    __syncthreads();
    for (int s = BB / 2; s; s >>= 1) {
        if (t < s) sm[t] += sm[t + s];
        __syncthreads();
    }
    if (t == 0) out[0] = (float)(-sm[0] / (double)BB);
}

extern "C" void kernel_launch(void* const* d_in, const int* in_sizes, int n_in,
                              void* d_out, int out_size) {
    const float* x = (const float*)d_in[0];
    const int*   y = (const int*)d_in[1];
    const float* W = (const float*)d_in[2];

    cudaFuncSetAttribute(k2_gemm, cudaFuncAttributeMaxDynamicSharedMemorySize, SMEM_TOTAL);

    k0_decode_y<<<1, BB>>>(y);
    k1_norm_x<<<BB, 128>>>(x);
    k1b_norm_w<<<CC / 8, 256>>>(W);
    k2_gemm<<<dim3(MT, NT), 256, SMEM_TOTAL>>>();
    k3_final<<<BB, 512>>>(W);
    k4_reduce<<<1, BB>>>((float*)d_out);
}

// round 9
// speedup vs baseline: 1.8063x; 1.8063x over previous
#include <cuda_runtime.h>
#include <cuda_fp16.h>
#include <cstdint>

// ArcFace loss, fused. FP16 HMMA GEMM with FP16 accumulate (m16n8k16.f16 —
// base sm_80; tcgen05 unavailable at compute_103 base, int8 IMMA measured 4x
// slow on sm_103). Normalized unit-vector operands: |elem| small -> fp16
// inputs more accurate than bf16; fp16 acc bounded by 1 (Cauchy-Schwarz).
// Exact fp32 target logit recomputed in k3.
// B=512, D=512, C=64000.
constexpr int BB = 512;
constexpr int DD = 512;
constexpr int CC = 64000;

constexpr int BM = 128, BN = 128, BK = 32;
constexpr int MT = BB / BM;    // 4
constexpr int NT = CC / BN;    // 500
constexpr int NSTG = DD / BK;  // 16
constexpr int AROW = 40;       // smem row stride (halfs); ldsm conflict-free
constexpr int STG  = BM * AROW * 2;   // 10240 B
constexpr int NPIPE = 5;

// dynamic smem layout
constexpr int A_OFF  = 0;                      // 5 stages
constexpr int B_OFF  = NPIPE * STG;            // 51200, 5 stages
constexpr int SY_OFF = B_OFF + NPIPE * STG;    // 102400: 128 ints
constexpr int RA_OFF = SY_OFF + 512;           // 102912: 128x4 floats
constexpr int SMEM_TOTAL = RA_OFF + 2048;      // 104960 (x2 CTA = 210KB <= 228KB)

__device__ float  g_xn[BB * DD];    // normalized x fp32 (k3 exact dot)
__device__ __half g_xnh[BB * DD];   // normalized x fp16 (GEMM A)
__device__ __half g_wnh[CC * DD];   // normalized W fp16 (GEMM B)
__device__ int    g_y[BB];
__device__ float  g_partial[MT * NT * BM];
__device__ double g_term[BB];

// ---------------- PTX helpers ----------------
__device__ __forceinline__ void ldsm4(uint32_t* r, uint32_t a) {
    asm volatile("ldmatrix.sync.aligned.m8n8.x4.shared.b16 {%0,%1,%2,%3}, [%4];"
        : "=r"(r[0]), "=r"(r[1]), "=r"(r[2]), "=r"(r[3]) : "r"(a));
}
// fp16 accumulate: C fragment = 2 regs (4 halfs); same element mapping as the
// fp32 variant's {c0,c1},{c2,c3} (reg0 = row, reg1 = row+8).
__device__ __forceinline__ void mma16816h(uint32_t* c, const uint32_t* a, uint32_t b0, uint32_t b1) {
    asm volatile("mma.sync.aligned.m16n8k16.row.col.f16.f16.f16.f16 "
        "{%0,%1}, {%2,%3,%4,%5}, {%6,%7}, {%0,%1};"
        : "+r"(c[0]), "+r"(c[1])
        : "r"(a[0]), "r"(a[1]), "r"(a[2]), "r"(a[3]), "r"(b0), "r"(b1));
}
__device__ __forceinline__ void cpasync16(uint32_t smem, const void* gptr) {
    asm volatile("cp.async.cg.shared.global [%0], [%1], 16;"
        :: "r"(smem), "l"(gptr) : "memory");
}
__device__ __forceinline__ void cpcommit() { asm volatile("cp.async.commit_group;" ::: "memory"); }
__device__ __forceinline__ void cpwait3() { asm volatile("cp.async.wait_group 3;" ::: "memory"); }

// ---------------------------------------------------------------------------
__global__ void k0_decode_y(const int* __restrict__ yw) {
    __shared__ int oddnz;
    int t = threadIdx.x;
    if (t == 0) oddnz = 0;
    __syncthreads();
    if (t < 256 && yw[2 * t + 1] != 0) atomicOr(&oddnz, 1);
    __syncthreads();
    if (oddnz == 0) g_y[t] = (int)((const long long*)yw)[t];
    else            g_y[t] = yw[t];
}

__global__ void k1_norm_x(const float* __restrict__ x) {
    int row = blockIdx.x;
    int t = threadIdx.x; // 128
    float4 v = ((const float4*)(x + row * DD))[t];
    float ss = v.x * v.x + v.y * v.y + v.z * v.z + v.w * v.w;
    #pragma unroll
    for (int o = 16; o; o >>= 1) ss += __shfl_xor_sync(0xffffffffu, ss, o);
    __shared__ float ws[4];
    if ((t & 31) == 0) ws[t >> 5] = ss;
    __syncthreads();
    float tot = ws[0] + ws[1] + ws[2] + ws[3];
    float sc = 1.0f / fmaxf(sqrtf(tot), 1e-12f);
    float4 o4 = make_float4(v.x * sc, v.y * sc, v.z * sc, v.w * sc);
    ((float4*)(g_xn + row * DD))[t] = o4;
    __half2 p0 = __floats2half2_rn(o4.x, o4.y);
    __half2 p1 = __floats2half2_rn(o4.z, o4.w);
    ((__half2*)(g_xnh + row * DD))[2 * t]     = p0;
    ((__half2*)(g_xnh + row * DD))[2 * t + 1] = p1;
}

// k1b: L2-normalize rows of W -> fp16. One warp per row, 8 rows per block.
__global__ __launch_bounds__(256) void k1b_norm_w(const float* __restrict__ Wm) {
    int wid = threadIdx.x >> 5, lane = threadIdx.x & 31;
    int row = blockIdx.x * 8 + wid;
    const float4* wr = (const float4*)(Wm + (size_t)row * DD);
    float4 v[4];
    float ss = 0.f;
    #pragma unroll
    for (int i = 0; i < 4; i++) {
        v[i] = wr[lane + i * 32];
        ss += v[i].x * v[i].x + v[i].y * v[i].y + v[i].z * v[i].z + v[i].w * v[i].w;
    }
    #pragma unroll
    for (int o = 16; o; o >>= 1) ss += __shfl_xor_sync(0xffffffffu, ss, o);
    float sc = 1.0f / fmaxf(sqrtf(ss), 1e-12f);
    __half2* out = (__half2*)(g_wnh + (size_t)row * DD);
    #pragma unroll
    for (int i = 0; i < 4; i++) {
        __half2 p0 = __floats2half2_rn(v[i].x * sc, v[i].y * sc);
        __half2 p1 = __floats2half2_rn(v[i].z * sc, v[i].w * sc);
        out[(lane + i * 32) * 2]     = p0;
        out[(lane + i * 32) * 2 + 1] = p1;
    }
}

// ---------------------------------------------------------------------------
// k2: fp16 HMMA GEMM, 256 threads / 8 warps (2x4, warp tile 64x32), 128Mx128N,
// BK=32, 5-stage cp.async (single sync/stage), 2 CTAs/SM, fp16 accumulators
// (32 acc regs -> slack for ptxas software pipelining).
// ---------------------------------------------------------------------------
__global__ __launch_bounds__(256, 2) void k2_gemm() {
    extern __shared__ char smem[];
    const uint32_t sb = (uint32_t)__cvta_generic_to_shared(smem);
    const int t = threadIdx.x, lane = t & 31, wp = t >> 5;
    const int wm = wp >> 2, wn = wp & 3;
    const int mt = blockIdx.x, nt = blockIdx.y;
    const int m0 = mt * BM, n0 = nt * BN;

    if (t < BM) ((int*)(smem + SY_OFF))[t] = g_y[m0 + t];

    const int pr = t >> 2, pc = (t & 3) * 8;
    const __half* gA0 = g_xnh + (m0 + pr) * DD + pc;
    const __half* gA1 = gA0 + 64 * DD;
    const __half* gB0 = g_wnh + (size_t)(n0 + pr) * DD + pc;
    const __half* gB1 = gB0 + 64 * DD;
    const uint32_t sA0 = sb + A_OFF + (pr * AROW + pc) * 2;
    const uint32_t sA1 = sA0 + 64 * AROW * 2;
    const uint32_t sB0 = sb + B_OFF + (pr * AROW + pc) * 2;
    const uint32_t sB1 = sB0 + 64 * AROW * 2;
    uint32_t wo = 0;

    auto fill = [&]() {
        cpasync16(sA0 + wo, gA0);
        cpasync16(sA1 + wo, gA1);
        cpasync16(sB0 + wo, gB0);
        cpasync16(sB1 + wo, gB1);
        gA0 += BK; gA1 += BK; gB0 += BK; gB1 += BK;
        wo += STG; if (wo == NPIPE * STG) wo = 0;
    };

    uint32_t acc[4][4][2];   // fp16x2 accumulators
    #pragma unroll
    for (int i = 0; i < 4; i++)
        #pragma unroll
        for (int j = 0; j < 4; j++) { acc[i][j][0] = 0u; acc[i][j][1] = 0u; }

    uint32_t aoff[4], boff[2];
    #pragma unroll
    for (int mf = 0; mf < 4; mf++)
        aoff[mf] = sb + A_OFF + ((wm * 64 + mf * 16 + (lane & 15)) * AROW + (lane >> 4) * 8) * 2;
    #pragma unroll
    for (int g = 0; g < 2; g++)
        boff[g] = sb + B_OFF + ((wn * 32 + g * 16 + (lane & 15)) * AROW + (lane >> 4) * 8) * 2;

    fill(); cpcommit();
    fill(); cpcommit();
    fill(); cpcommit();
    fill(); cpcommit();

    uint32_t ro = 0;
    for (int ks = 0; ks < NSTG; ks++) {
        cpwait3();
        __syncthreads();
        if (ks + 4 < NSTG) fill();
        cpcommit();

        #pragma unroll
        for (int kc = 0; kc < 2; kc++) {
            uint32_t bfrag[2][4];
            ldsm4(bfrag[0], boff[0] + ro + kc * 32);
            ldsm4(bfrag[1], boff[1] + ro + kc * 32);
            #pragma unroll
            for (int mf = 0; mf < 4; mf++) {
                uint32_t afrag[4];
                ldsm4(afrag, aoff[mf] + ro + kc * 32);
                #pragma unroll
                for (int nf = 0; nf < 4; nf++) {
                    int g = nf >> 1, h = nf & 1;
                    mma16816h(acc[mf][nf], afrag, bfrag[g][h], bfrag[g][2 + h]);
                }
            }
        }
        ro += STG; if (ro == NPIPE * STG) ro = 0;
    }
    __syncthreads();

    // epilogue: theta = acc (pre-normalized operands); unpack fp16 pairs
    const int* sy = (const int*)(smem + SY_OFF);
    float* rowacc = (float*)(smem + RA_OFF);
    #pragma unroll
    for (int mf = 0; mf < 4; mf++) {
        #pragma unroll
        for (int h = 0; h < 2; h++) {
            int row = wm * 64 + mf * 16 + h * 8 + (lane >> 2);
            int yrel = sy[row] - n0;
            float rsum = 0.f;
            #pragma unroll
            for (int nf = 0; nf < 4; nf++) {
                int nl = wn * 32 + nf * 8 + (lane & 3) * 2;
                float2 th = __half22float2(*(const __half2*)&acc[mf][nf][h]);
                float e0 = __expf(64.0f * th.x);
                float e1 = __expf(64.0f * th.y);
                rsum += (nl     == yrel) ? 0.f : e0;
                rsum += (nl + 1 == yrel) ? 0.f : e1;
            }
            rsum += __shfl_xor_sync(0xffffffffu, rsum, 1);
            rsum += __shfl_xor_sync(0xffffffffu, rsum, 2);
            if ((lane & 3) == 0) rowacc[row * 4 + wn] = rsum;
        }
    }
    __syncthreads();
    if (t < BM)
        g_partial[(mt * NT + nt) * BM + t] =
            (rowacc[t * 4] + rowacc[t * 4 + 1]) + (rowacc[t * 4 + 2] + rowacc[t * 4 + 3]);
}

// ---------------------------------------------------------------------------
// k3: per-row finalize; exact fp32 target logit. One block per row, 512 thr.
// ---------------------------------------------------------------------------
__global__ __launch_bounds__(512) void k3_final(const float* __restrict__ Wm) {
    __shared__ double sd[512];
    __shared__ float  sf[128], sg[128];
    int b = blockIdx.x, t = threadIdx.x;
    int yb = g_y[b];
    int mt = b >> 7, ml = b & 127;

    double ex = (t < NT) ? (double)g_partial[(mt * NT + t) * BM + ml] : 0.0;

    if (t < 128) {
        float4 wv = ((const float4*)(Wm + (size_t)yb * DD))[t];
        float4 xv = ((const float4*)(g_xn + b * DD))[t];
        sf[t] = wv.x * xv.x + wv.y * xv.y + wv.z * xv.z + wv.w * xv.w;
        sg[t] = wv.x * wv.x + wv.y * wv.y + wv.z * wv.z + wv.w * wv.w;
    }
    sd[t] = ex;
    __syncthreads();
    for (int s = 256; s >= 128; s >>= 1) {
        if (t < s) sd[t] += sd[t + s];
        __syncthreads();
    }
    for (int s = 64; s; s >>= 1) {
        if (t < s) { sd[t] += sd[t + s]; sf[t] += sf[t + s]; sg[t] += sg[t + s]; }
        __syncthreads();
    }
    if (t == 0) {
        double tgt = (double)sf[0] / fmax(sqrt((double)sg[0]), 1e-12);
        double tc = fmin(fmax(tgt, -1.0 + 1e-7), 1.0 - 1e-7);
        double num = 64.0 * cos(acos(tc) + 0.5);
        double den = exp(num) + sd[0];
        g_term[b] = num - log(den);
    }
}

__global__ void k4_reduce(float* __restrict__ out) {
    __shared__ double sm[BB];
    int t = threadIdx.x;
    sm[t] = g_term[t];
    __syncthreads();
    for (int s = BB / 2; s; s >>= 1) {
        if (t < s) sm[t] += sm[t + s];
        __syncthreads();
    }
    if (t == 0) out[0] = (float)(-sm[0] / (double)BB);
}

extern "C" void kernel_launch(void* const* d_in, const int* in_sizes, int n_in,
                              void* d_out, int out_size) {
    const float* x = (const float*)d_in[0];
    const int*   y = (const int*)d_in[1];
    const float* W = (const float*)d_in[2];

    cudaFuncSetAttribute(k2_gemm, cudaFuncAttributeMaxDynamicSharedMemorySize, SMEM_TOTAL);

    k0_decode_y<<<1, BB>>>(y);
    k1_norm_x<<<BB, 128>>>(x);
    k1b_norm_w<<<CC / 8, 256>>>(W);
    k2_gemm<<<dim3(MT, NT), 256, SMEM_TOTAL>>>();
    k3_final<<<BB, 512>>>(W);
    k4_reduce<<<1, BB>>>((float*)d_out);
}

// round 10
// speedup vs baseline: 1.9035x; 1.0538x over previous
#include <cuda_runtime.h>
#include <cuda_fp16.h>
#include <cstdint>

// ArcFace loss, fused. FP16 HMMA GEMM, fp16 accumulate, warp tile 64x64
// (smem-crossbar traffic was the co-limiter at warp 64x32: ~530 crossbar-cyc
// vs 512 tensor-cyc per stage; 64x64 cuts ldsm bytes/MAC by 33%).
// B=512, D=512, C=64000.
constexpr int BB = 512;
constexpr int DD = 512;
constexpr int CC = 64000;

constexpr int BM = 256, BN = 128, BK = 32;
constexpr int MT = BB / BM;    // 2
constexpr int NT = CC / BN;    // 500
constexpr int NSTG = DD / BK;  // 16
constexpr int AROW = 40;       // smem row stride (halfs); ldsm conflict-free
constexpr int A_STG = BM * AROW * 2;   // 20480 B
constexpr int B_STG = BN * AROW * 2;   // 10240 B
constexpr int NPIPE = 3;

// dynamic smem layout
constexpr int A_OFF  = 0;                       // 3 stages
constexpr int B_OFF  = NPIPE * A_STG;           // 61440, 3 stages
constexpr int SY_OFF = B_OFF + NPIPE * B_STG;   // 92160: 256 ints
constexpr int RA_OFF = SY_OFF + 1024;           // 93184: 256x2 floats
constexpr int SMEM_TOTAL = RA_OFF + 2048;       // 95232 (x2 CTA = 190KB <= 228KB)

__device__ float  g_xn[BB * DD];    // normalized x fp32 (k3 exact dot)
__device__ __half g_xnh[BB * DD];   // normalized x fp16 (GEMM A)
__device__ __half g_wnh[CC * DD];   // normalized W fp16 (GEMM B)
__device__ int    g_y[BB];
__device__ float  g_partial[MT * NT * BM];
__device__ double g_term[BB];

// ---------------- PTX helpers ----------------
__device__ __forceinline__ void ldsm4(uint32_t* r, uint32_t a) {
    asm volatile("ldmatrix.sync.aligned.m8n8.x4.shared.b16 {%0,%1,%2,%3}, [%4];"
        : "=r"(r[0]), "=r"(r[1]), "=r"(r[2]), "=r"(r[3]) : "r"(a));
}
__device__ __forceinline__ void mma16816h(uint32_t* c, const uint32_t* a, uint32_t b0, uint32_t b1) {
    asm volatile("mma.sync.aligned.m16n8k16.row.col.f16.f16.f16.f16 "
        "{%0,%1}, {%2,%3,%4,%5}, {%6,%7}, {%0,%1};"
        : "+r"(c[0]), "+r"(c[1])
        : "r"(a[0]), "r"(a[1]), "r"(a[2]), "r"(a[3]), "r"(b0), "r"(b1));
}
__device__ __forceinline__ void cpasync16(uint32_t smem, const void* gptr) {
    asm volatile("cp.async.cg.shared.global [%0], [%1], 16;"
        :: "r"(smem), "l"(gptr) : "memory");
}
__device__ __forceinline__ void cpcommit() { asm volatile("cp.async.commit_group;" ::: "memory"); }
__device__ __forceinline__ void cpwait1() { asm volatile("cp.async.wait_group 1;" ::: "memory"); }

// ---------------------------------------------------------------------------
__global__ void k0_decode_y(const int* __restrict__ yw) {
    __shared__ int oddnz;
    int t = threadIdx.x;
    if (t == 0) oddnz = 0;
    __syncthreads();
    if (t < 256 && yw[2 * t + 1] != 0) atomicOr(&oddnz, 1);
    __syncthreads();
    if (oddnz == 0) g_y[t] = (int)((const long long*)yw)[t];
    else            g_y[t] = yw[t];
}

__global__ void k1_norm_x(const float* __restrict__ x) {
    int row = blockIdx.x;
    int t = threadIdx.x; // 128
    float4 v = ((const float4*)(x + row * DD))[t];
    float ss = v.x * v.x + v.y * v.y + v.z * v.z + v.w * v.w;
    #pragma unroll
    for (int o = 16; o; o >>= 1) ss += __shfl_xor_sync(0xffffffffu, ss, o);
    __shared__ float ws[4];
    if ((t & 31) == 0) ws[t >> 5] = ss;
    __syncthreads();
    float tot = ws[0] + ws[1] + ws[2] + ws[3];
    float sc = 1.0f / fmaxf(sqrtf(tot), 1e-12f);
    float4 o4 = make_float4(v.x * sc, v.y * sc, v.z * sc, v.w * sc);
    ((float4*)(g_xn + row * DD))[t] = o4;
    __half2 p0 = __floats2half2_rn(o4.x, o4.y);
    __half2 p1 = __floats2half2_rn(o4.z, o4.w);
    ((__half2*)(g_xnh + row * DD))[2 * t]     = p0;
    ((__half2*)(g_xnh + row * DD))[2 * t + 1] = p1;
}

// k1b: L2-normalize rows of W -> fp16. One warp per row, 8 rows per block.
__global__ __launch_bounds__(256) void k1b_norm_w(const float* __restrict__ Wm) {
    int wid = threadIdx.x >> 5, lane = threadIdx.x & 31;
    int row = blockIdx.x * 8 + wid;
    const float4* wr = (const float4*)(Wm + (size_t)row * DD);
    float4 v[4];
    float ss = 0.f;
    #pragma unroll
    for (int i = 0; i < 4; i++) {
        v[i] = wr[lane + i * 32];
        ss += v[i].x * v[i].x + v[i].y * v[i].y + v[i].z * v[i].z + v[i].w * v[i].w;
    }
    #pragma unroll
    for (int o = 16; o; o >>= 1) ss += __shfl_xor_sync(0xffffffffu, ss, o);
    float sc = 1.0f / fmaxf(sqrtf(ss), 1e-12f);
    __half2* out = (__half2*)(g_wnh + (size_t)row * DD);
    #pragma unroll
    for (int i = 0; i < 4; i++) {
        __half2 p0 = __floats2half2_rn(v[i].x * sc, v[i].y * sc);
        __half2 p1 = __floats2half2_rn(v[i].z * sc, v[i].w * sc);
        out[(lane + i * 32) * 2]     = p0;
        out[(lane + i * 32) * 2 + 1] = p1;
    }
}

// ---------------------------------------------------------------------------
// k2: fp16 HMMA GEMM, 256 threads / 8 warps (4x2, warp tile 64x64), 256Mx128N,
// BK=32, 3-stage cp.async (single sync/stage), 2 CTAs/SM, fp16 accumulators.
// ---------------------------------------------------------------------------
__global__ __launch_bounds__(256, 2) void k2_gemm() {
    extern __shared__ char smem[];
    const uint32_t sb = (uint32_t)__cvta_generic_to_shared(smem);
    const int t = threadIdx.x, lane = t & 31, wp = t >> 5;
    const int wm = wp >> 1, wn = wp & 1;       // 4x2 warps, tile 64x64
    const int mt = blockIdx.x, nt = blockIdx.y;
    const int m0 = mt * BM, n0 = nt * BN;

    if (t < BM) ((int*)(smem + SY_OFF))[t] = g_y[m0 + t];

    // producers: A 4 rows/thread (stride 64), B 2 rows/thread (stride 64)
    const int pr = t >> 2, pc = (t & 3) * 8;
    const __half* gA = g_xnh + (m0 + pr) * DD + pc;
    const __half* gB = g_wnh + (size_t)(n0 + pr) * DD + pc;
    const uint32_t sA = sb + A_OFF + (pr * AROW + pc) * 2;
    const uint32_t sB = sb + B_OFF + (pr * AROW + pc) * 2;
    constexpr uint32_t ARS = 64 * AROW * 2;   // 64-row stride in smem bytes
    uint32_t woA = 0, woB = 0;

    auto fill = [&]() {
        cpasync16(sA + woA,           gA);
        cpasync16(sA + woA + ARS,     gA + 64 * DD);
        cpasync16(sA + woA + 2 * ARS, gA + 128 * DD);
        cpasync16(sA + woA + 3 * ARS, gA + 192 * DD);
        cpasync16(sB + woB,           gB);
        cpasync16(sB + woB + ARS,     gB + 64 * DD);
        gA += BK; gB += BK;
        woA += A_STG; if (woA == NPIPE * A_STG) woA = 0;
        woB += B_STG; if (woB == NPIPE * B_STG) woB = 0;
    };

    uint32_t acc[4][8][2];   // fp16x2 accumulators, 64 regs
    #pragma unroll
    for (int i = 0; i < 4; i++)
        #pragma unroll
        for (int j = 0; j < 8; j++) { acc[i][j][0] = 0u; acc[i][j][1] = 0u; }

    uint32_t aoff[4], boff[4];
    #pragma unroll
    for (int mf = 0; mf < 4; mf++)
        aoff[mf] = sb + A_OFF + ((wm * 64 + mf * 16 + (lane & 15)) * AROW + (lane >> 4) * 8) * 2;
    #pragma unroll
    for (int g = 0; g < 4; g++)
        boff[g] = sb + B_OFF + ((wn * 64 + g * 16 + (lane & 15)) * AROW + (lane >> 4) * 8) * 2;

    fill(); cpcommit();
    fill(); cpcommit();

    uint32_t roA = 0, roB = 0;
    for (int ks = 0; ks < NSTG; ks++) {
        cpwait1();
        __syncthreads();
        if (ks + 2 < NSTG) fill();
        cpcommit();

        #pragma unroll
        for (int kc = 0; kc < 2; kc++) {
            uint32_t bfrag[4][4];
            #pragma unroll
            for (int g = 0; g < 4; g++)
                ldsm4(bfrag[g], boff[g] + roB + kc * 32);
            #pragma unroll
            for (int mf = 0; mf < 4; mf++) {
                uint32_t afrag[4];
                ldsm4(afrag, aoff[mf] + roA + kc * 32);
                #pragma unroll
                for (int nf = 0; nf < 8; nf++) {
                    int g = nf >> 1, h = nf & 1;
                    mma16816h(acc[mf][nf], afrag, bfrag[g][h], bfrag[g][2 + h]);
                }
            }
        }
        roA += A_STG; if (roA == NPIPE * A_STG) roA = 0;
        roB += B_STG; if (roB == NPIPE * B_STG) roB = 0;
    }
    __syncthreads();

    // epilogue: theta = acc; exp + mask + row-sum
    const int* sy = (const int*)(smem + SY_OFF);
    float* rowacc = (float*)(smem + RA_OFF);
    #pragma unroll
    for (int mf = 0; mf < 4; mf++) {
        #pragma unroll
        for (int h = 0; h < 2; h++) {
            int row = wm * 64 + mf * 16 + h * 8 + (lane >> 2);
            int yrel = sy[row] - n0;
            float rsum = 0.f;
            #pragma unroll
            for (int nf = 0; nf < 8; nf++) {
                int nl = wn * 64 + nf * 8 + (lane & 3) * 2;
                float2 th = __half22float2(*(const __half2*)&acc[mf][nf][h]);
                float e0 = __expf(64.0f * th.x);
                float e1 = __expf(64.0f * th.y);
                rsum += (nl     == yrel) ? 0.f : e0;
                rsum += (nl + 1 == yrel) ? 0.f : e1;
            }
            rsum += __shfl_xor_sync(0xffffffffu, rsum, 1);
            rsum += __shfl_xor_sync(0xffffffffu, rsum, 2);
            if ((lane & 3) == 0) rowacc[row * 2 + wn] = rsum;
        }
    }
    __syncthreads();
    if (t < BM)
        g_partial[(mt * NT + nt) * BM + t] = rowacc[t * 2] + rowacc[t * 2 + 1];
}

// ---------------------------------------------------------------------------
// k3: per-row finalize; exact fp32 target logit. One block per row, 512 thr.
// ---------------------------------------------------------------------------
__global__ __launch_bounds__(512) void k3_final(const float* __restrict__ Wm) {
    __shared__ double sd[512];
    __shared__ float  sf[128], sg[128];
    int b = blockIdx.x, t = threadIdx.x;
    int yb = g_y[b];
    int mt = b >> 8, ml = b & 255;

    double ex = (t < NT) ? (double)g_partial[(mt * NT + t) * BM + ml] : 0.0;

    if (t < 128) {
        float4 wv = ((const float4*)(Wm + (size_t)yb * DD))[t];
        float4 xv = ((const float4*)(g_xn + b * DD))[t];
        sf[t] = wv.x * xv.x + wv.y * xv.y + wv.z * xv.z + wv.w * xv.w;
        sg[t] = wv.x * wv.x + wv.y * wv.y + wv.z * wv.z + wv.w * wv.w;
    }
    sd[t] = ex;
    __syncthreads();
    for (int s = 256; s >= 128; s >>= 1) {
        if (t < s) sd[t] += sd[t + s];
        __syncthreads();
    }
    for (int s = 64; s; s >>= 1) {
        if (t < s) { sd[t] += sd[t + s]; sf[t] += sf[t + s]; sg[t] += sg[t + s]; }
        __syncthreads();
    }
    if (t == 0) {
        double tgt = (double)sf[0] / fmax(sqrt((double)sg[0]), 1e-12);
        double tc = fmin(fmax(tgt, -1.0 + 1e-7), 1.0 - 1e-7);
        double num = 64.0 * cos(acos(tc) + 0.5);
        double den = exp(num) + sd[0];
        g_term[b] = num - log(den);
    }
}

__global__ void k4_reduce(float* __restrict__ out) {
    __shared__ double sm[BB];
    int t = threadIdx.x;
    sm[t] = g_term[t];
    __syncthreads();
    for (int s = BB / 2; s; s >>= 1) {
        if (t < s) sm[t] += sm[t + s];
        __syncthreads();
    }
    if (t == 0) out[0] = (float)(-sm[0] / (double)BB);
}

extern "C" void kernel_launch(void* const* d_in, const int* in_sizes, int n_in,
                              void* d_out, int out_size) {
    const float* x = (const float*)d_in[0];
    const int*   y = (const int*)d_in[1];
    const float* W = (const float*)d_in[2];

    cudaFuncSetAttribute(k2_gemm, cudaFuncAttributeMaxDynamicSharedMemorySize, SMEM_TOTAL);

    k0_decode_y<<<1, BB>>>(y);
    k1_norm_x<<<BB, 128>>>(x);
    k1b_norm_w<<<CC / 8, 256>>>(W);
    k2_gemm<<<dim3(MT, NT), 256, SMEM_TOTAL>>>();
    k3_final<<<BB, 512>>>(W);
    k4_reduce<<<1, BB>>>((float*)d_out);
}